// round 12
// baseline (speedup 1.0000x reference)
#include <cuda_runtime.h>
#include <cuda_fp16.h>
#include <math.h>
#include <stdint.h>

#define R_DIM 64
#define I_DIM 512
#define N_DIM 4
#define E_DIM 256
#define H_DIM 8
#define D_DIM 32
#define T_TOK (R_DIM * I_DIM * N_DIM)                 /* 131072 tokens */
#define OUT_ELEMS ((size_t)T_TOK * E_DIM)             /* 33554432 */
#define PROB_ELEMS ((size_t)H_DIM * N_DIM * I_DIM * I_DIM) /* 8388608 */

// KH=64 path (proj/logits): pitch 144, 3 stages.  KH=32 path (context): pitch 80, 4 stages.
#define SM64 (3 * 2 * 128 * 144)   /* 110592 */
#define SM32 (4 * 2 * 128 * 80)    /*  81920 */
#define GT 128                     /* threads per GEMM block (4 warps, 64x64 tiles) */

// ---------------- scratch (alloc-free rule: __device__ globals) ----------------
__device__ __half gh_x[T_TOK * E_DIM];
__device__ __half gh_w[4 * E_DIM * E_DIM];
__device__ __half gh_q[T_TOK * E_DIM];
__device__ __half gh_k[T_TOK * E_DIM];
__device__ __half gh_v[T_TOK * E_DIM];
__device__ __half gh_ctx[T_TOK * E_DIM];
__device__ __half gh_pr[PROB_ELEMS];      // fp16 probs for context GEMM
__device__ float g_probs[PROB_ELEMS];     // fallback f32 probs
__device__ unsigned char g_bkt[N_DIM * I_DIM * I_DIM];

// ---------------- low-level helpers ---------------------------------------------
__device__ __forceinline__ uint32_t smem_u32(const void* p) {
    uint32_t a;
    asm("{ .reg .u64 t; cvta.to.shared.u64 t, %1; cvt.u32.u64 %0, t; }" : "=r"(a) : "l"(p));
    return a;
}
__device__ __forceinline__ void cp16(uint32_t saddr, const void* g) {
    asm volatile("cp.async.cg.shared.global [%0], [%1], 16;" :: "r"(saddr), "l"(g));
}
#define CP_COMMIT() asm volatile("cp.async.commit_group;" ::: "memory")
template<int N> __device__ __forceinline__ void cp_wait() {
    if (N == 1) asm volatile("cp.async.wait_group 1;" ::: "memory");
    else        asm volatile("cp.async.wait_group 2;" ::: "memory");
}
__device__ __forceinline__ void ldsm4(uint32_t& r0, uint32_t& r1, uint32_t& r2, uint32_t& r3,
                                      uint32_t addr) {
    asm volatile("ldmatrix.sync.aligned.m8n8.x4.shared.b16 {%0,%1,%2,%3}, [%4];"
                 : "=r"(r0), "=r"(r1), "=r"(r2), "=r"(r3) : "r"(addr));
}
__device__ __forceinline__ void ldsm4t(uint32_t& r0, uint32_t& r1, uint32_t& r2, uint32_t& r3,
                                       uint32_t addr) {
    asm volatile("ldmatrix.sync.aligned.m8n8.x4.trans.shared.b16 {%0,%1,%2,%3}, [%4];"
                 : "=r"(r0), "=r"(r1), "=r"(r2), "=r"(r3) : "r"(addr));
}
__device__ __forceinline__ void mma16816(float c[4], const uint32_t a[4], const uint32_t b[2]) {
    asm volatile(
        "mma.sync.aligned.m16n8k16.row.col.f32.f16.f16.f32 "
        "{%0,%1,%2,%3}, {%4,%5,%6,%7}, {%8,%9}, {%0,%1,%2,%3};"
        : "+f"(c[0]), "+f"(c[1]), "+f"(c[2]), "+f"(c[3])
        : "r"(a[0]), "r"(a[1]), "r"(a[2]), "r"(a[3]), "r"(b[0]), "r"(b[1]));
}

// Tile loader: 128 rows x KH halves via cp.async, GT threads.
// src(row,g) = base + (row>>5)*rowGrpStride + (row&31)*rowStride + (g>>2)*kGrpStride + (g&3)*8
template<int KH>
__device__ __forceinline__ void load_tile(uint32_t sdst, const __half* base,
                                          size_t rowStride, size_t rowGrpStride,
                                          size_t kGrpStride, int tid) {
    constexpr int PITCH = KH * 2 + 16;
    constexpr int NG = KH / 8;
#pragma unroll
    for (int it = 0; it < (128 * NG) / GT; it++) {
        int idx = tid + it * GT;
        int row = idx / NG, g = idx % NG;
        const __half* src = base + (size_t)(row >> 5) * rowGrpStride
                                 + (size_t)(row & 31) * rowStride
                                 + (size_t)(g >> 2) * kGrpStride + (g & 3) * 8;
        cp16(sdst + row * PITCH + g * 16, src);
    }
}

// --------- per-warp compute on one KH-deep K chunk (warp tile 64x64) ------------
template<int KH, bool BTRANS>
__device__ __forceinline__ void compute_chunk(uint32_t bufA, uint32_t bufB,
                                              int wm, int wn, int lane, float acc[4][8][4]) {
    constexpr int PITCH = KH * 2 + 16;
    uint32_t aoff = bufA + (uint32_t)((wm + (lane & 15)) * PITCH + ((lane >> 4) << 4));
    uint32_t boff;
    if (BTRANS) {
        // tile rows = rgrp*32 + j; cols = d. Warp covers rgrp base (wn>>5) and +1.
        boff = bufB + (uint32_t)(((wn >> 5) * 32 + (lane & 15)) * PITCH
                                 + ((lane >> 4) << 4));
    } else {
        boff = bufB + (uint32_t)((wn + ((lane >> 4) << 3) + (lane & 7)) * PITCH
                                 + (((lane >> 3) & 1) << 4));
    }
#pragma unroll
    for (int ks = 0; ks < KH / 16; ks++) {
        uint32_t a[4][4];
#pragma unroll
        for (int fq = 0; fq < 4; fq++)
            ldsm4(a[fq][0], a[fq][1], a[fq][2], a[fq][3], aoff + fq * (16 * PITCH) + ks * 32);
        uint32_t b[8][2];
        if (BTRANS) {
#pragma unroll
            for (int rg = 0; rg < 2; rg++)
#pragma unroll
                for (int p = 0; p < 2; p++) {
                    uint32_t r0, r1, r2, r3;
                    ldsm4t(r0, r1, r2, r3,
                           boff + rg * (32 * PITCH) + ks * (16 * PITCH) + p * 32);
                    b[rg * 4 + p * 2][0] = r0; b[rg * 4 + p * 2][1] = r1;
                    b[rg * 4 + p * 2 + 1][0] = r2; b[rg * 4 + p * 2 + 1][1] = r3;
                }
        } else {
#pragma unroll
            for (int p = 0; p < 4; p++) {
                uint32_t r0, r1, r2, r3;
                ldsm4(r0, r1, r2, r3, boff + p * (16 * PITCH) + ks * 32);
                b[p * 2][0] = r0; b[p * 2][1] = r1;
                b[p * 2 + 1][0] = r2; b[p * 2 + 1][1] = r3;
            }
        }
#pragma unroll
        for (int fq = 0; fq < 4; fq++)
#pragma unroll
            for (int g = 0; g < 8; g++)
                mma16816(acc[fq][g], a[fq], b[g]);
    }
}

// NST-stage cp.async mainloop. NCH >= NST-1.
template<int KH, int NST, bool BTRANS>
__device__ __forceinline__ void gemm_main(
    const __half* Ab, size_t rsA, size_t rgA, size_t kgA, size_t chA,
    const __half* Bb, size_t rsB, size_t rgB, size_t kgB, size_t chB,
    int NCH, uint32_t sbase, int tid, int wm, int wn, int lane, float acc[4][8][4])
{
    constexpr int TILEB = 128 * (KH * 2 + 16);
    constexpr int STGB = 2 * TILEB;
#pragma unroll
    for (int s = 0; s < NST - 1; s++) {
        load_tile<KH>(sbase + s * STGB, Ab + (size_t)s * chA, rsA, rgA, kgA, tid);
        load_tile<KH>(sbase + s * STGB + TILEB, Bb + (size_t)s * chB, rsB, rgB, kgB, tid);
        CP_COMMIT();
    }
    int cs = 0, ls = NST - 1;
    for (int ch = 0; ch < NCH; ch++) {
        cp_wait<NST - 2>();
        __syncthreads();
        if (ch + NST - 1 < NCH) {
            uint32_t so = sbase + ls * STGB;
            load_tile<KH>(so, Ab + (size_t)(ch + NST - 1) * chA, rsA, rgA, kgA, tid);
            load_tile<KH>(so + TILEB, Bb + (size_t)(ch + NST - 1) * chB, rsB, rgB, kgB, tid);
        }
        CP_COMMIT();
        if (++ls == NST) ls = 0;
        compute_chunk<KH, BTRANS>(sbase + cs * STGB, sbase + cs * STGB + TILEB,
                                  wm, wn, lane, acc);
        if (++cs == NST) cs = 0;
    }
}

// T5 bucketize (verified exact vs jnp.linspace/searchsorted in R2/R3)
__device__ __forceinline__ int bucket_of(int dist) {
    int ad = dist < 0 ? -dist : dist;
    float v = (float)ad;
    int lo = 0, hi = 62;
#pragma unroll
    for (int it = 0; it < 6; it++) {
        int mid = (lo + hi) >> 1;
        float b = (float)((50000.0 * (double)mid) / 62.0);
        if (b >= v) hi = mid; else lo = mid + 1;
    }
    return lo;
}
__global__ __launch_bounds__(256) void bucket_kernel(
    const int* __restrict__ dist, unsigned char* __restrict__ bkt) {
    int idx = blockIdx.x * 256 + threadIdx.x;
    bkt[idx] = (unsigned char)bucket_of(dist[idx]);
}

// ---------------- f32 -> f16 bulk converts --------------------------------------
__global__ __launch_bounds__(256) void conv_f16(
    const float* __restrict__ src, __half* __restrict__ dst) {
    size_t idx = ((size_t)blockIdx.x * 256 + threadIdx.x) * 8;
    float4 a = *(const float4*)(src + idx);
    float4 b = *(const float4*)(src + idx + 4);
    __half2 h0 = __float22half2_rn(make_float2(a.x, a.y));
    __half2 h1 = __float22half2_rn(make_float2(a.z, a.w));
    __half2 h2 = __float22half2_rn(make_float2(b.x, b.y));
    __half2 h3 = __float22half2_rn(make_float2(b.z, b.w));
    uint4 u;
    u.x = *(uint32_t*)&h0; u.y = *(uint32_t*)&h1;
    u.z = *(uint32_t*)&h2; u.w = *(uint32_t*)&h3;
    *(uint4*)(dst + idx) = u;
}
__global__ __launch_bounds__(256) void conv_w4(
    const float* __restrict__ w0, const float* __restrict__ w1,
    const float* __restrict__ w2, const float* __restrict__ w3,
    __half* __restrict__ dst) {
    const float* src = (blockIdx.y == 0) ? w0 : (blockIdx.y == 1) ? w1
                      : (blockIdx.y == 2) ? w2 : w3;
    size_t idx = ((size_t)blockIdx.x * 256 + threadIdx.x) * 8;
    float4 a = *(const float4*)(src + idx);
    float4 b = *(const float4*)(src + idx + 4);
    __half2 h0 = __float22half2_rn(make_float2(a.x, a.y));
    __half2 h1 = __float22half2_rn(make_float2(a.z, a.w));
    __half2 h2 = __float22half2_rn(make_float2(b.x, b.y));
    __half2 h3 = __float22half2_rn(make_float2(b.z, b.w));
    uint4 u;
    u.x = *(uint32_t*)&h0; u.y = *(uint32_t*)&h1;
    u.z = *(uint32_t*)&h2; u.w = *(uint32_t*)&h3;
    *(uint4*)(dst + (size_t)blockIdx.y * E_DIM * E_DIM + idx) = u;
}

// ============ fused QKV projection: z selects (W, bias, out, scale) =============
__global__ __launch_bounds__(GT, 2) void proj_qkv(
    const __half* __restrict__ A, const __half* __restrict__ Wall,
    const float* __restrict__ bq, const float* __restrict__ bk,
    const float* __restrict__ bv,
    __half* __restrict__ oq, __half* __restrict__ ok, __half* __restrict__ ov,
    float scaleq)
{
    extern __shared__ __align__(16) char smem[];
    const int tid = threadIdx.x, warp = tid >> 5, lane = tid & 31;
    const int wm = (warp >> 1) * 64, wn = (warp & 1) * 64;
    const int t0 = blockIdx.x * 128, f0 = blockIdx.y * 128;
    const int z = blockIdx.z;
    const __half* W = Wall + (size_t)z * E_DIM * E_DIM;
    const float* bias = (z == 0) ? bq : (z == 1) ? bk : bv;
    __half* C = (z == 0) ? oq : (z == 1) ? ok : ov;
    const float scale = (z == 0) ? scaleq : 1.0f;

    float acc[4][8][4];
#pragma unroll
    for (int fq = 0; fq < 4; fq++)
#pragma unroll
        for (int g = 0; g < 8; g++)
#pragma unroll
            for (int c = 0; c < 4; c++) acc[fq][g][c] = 0.f;

    gemm_main<64, 3, false>(
        A + (size_t)t0 * E_DIM, E_DIM, 32 * E_DIM, 32, 64,
        W + (size_t)f0 * E_DIM, E_DIM, 32 * E_DIM, 32, 64,
        E_DIM / 64, smem_u32(smem), tid, wm, wn, lane, acc);

    const int grp = lane >> 2, qid = lane & 3;
#pragma unroll
    for (int fq = 0; fq < 4; fq++)
#pragma unroll
        for (int rr = 0; rr < 2; rr++) {
            int i = t0 + wm + fq * 16 + grp + rr * 8;
#pragma unroll
            for (int g = 0; g < 8; g++) {
                int col = f0 + wn + g * 8 + qid * 2;
                float2 o;
                o.x = (acc[fq][g][rr * 2 + 0] + bias[col + 0]) * scale;
                o.y = (acc[fq][g][rr * 2 + 1] + bias[col + 1]) * scale;
                *(__half2*)(C + (size_t)i * E_DIM + col) = __float22half2_rn(o);
            }
        }
}

// ===================== output projection: f16 in, f32 out =======================
__global__ __launch_bounds__(GT, 2) void proj_out(
    const __half* __restrict__ A, const __half* __restrict__ W,
    const float* __restrict__ bias, float* __restrict__ C)
{
    extern __shared__ __align__(16) char smem[];
    const int tid = threadIdx.x, warp = tid >> 5, lane = tid & 31;
    const int wm = (warp >> 1) * 64, wn = (warp & 1) * 64;
    const int t0 = blockIdx.x * 128, f0 = blockIdx.y * 128;

    float acc[4][8][4];
#pragma unroll
    for (int fq = 0; fq < 4; fq++)
#pragma unroll
        for (int g = 0; g < 8; g++)
#pragma unroll
            for (int c = 0; c < 4; c++) acc[fq][g][c] = 0.f;

    gemm_main<64, 3, false>(
        A + (size_t)t0 * E_DIM, E_DIM, 32 * E_DIM, 32, 64,
        W + (size_t)f0 * E_DIM, E_DIM, 32 * E_DIM, 32, 64,
        E_DIM / 64, smem_u32(smem), tid, wm, wn, lane, acc);

    const int grp = lane >> 2, qid = lane & 3;
#pragma unroll
    for (int fq = 0; fq < 4; fq++)
#pragma unroll
        for (int rr = 0; rr < 2; rr++) {
            int i = t0 + wm + fq * 16 + grp + rr * 8;
#pragma unroll
            for (int g = 0; g < 8; g++) {
                int col = f0 + wn + g * 8 + qid * 2;
                float2 o;
                o.x = acc[fq][g][rr * 2 + 0] + bias[col + 0];
                o.y = acc[fq][g][rr * 2 + 1] + bias[col + 1];
                *(float2*)(C + (size_t)i * E_DIM + col) = o;
            }
        }
}

// =========== logits: out[h,n,i,j] = sum_{r,d} q·k + rel[bucket[n,i,j],h] =========
__global__ __launch_bounds__(GT, 2) void logits_gemm(
    const __half* __restrict__ q, const __half* __restrict__ k,
    const unsigned char* __restrict__ bkt, const float* __restrict__ rel,
    float* __restrict__ out)
{
    extern __shared__ __align__(16) char smem[];
    const int tid = threadIdx.x, warp = tid >> 5, lane = tid & 31;
    const int wm = (warp >> 1) * 64, wn = (warp & 1) * 64;
    const int i0 = blockIdx.x * 128, j0 = blockIdx.y * 128;
    const int z = blockIdx.z, h = z >> 2, n = z & 3;

    float acc[4][8][4];
#pragma unroll
    for (int fq = 0; fq < 4; fq++)
#pragma unroll
        for (int g = 0; g < 8; g++)
#pragma unroll
            for (int c = 0; c < 4; c++) acc[fq][g][c] = 0.f;

    // K chunk = 2 r values: [r0 d0..31 | r1 d0..31]; same packing both operands.
    gemm_main<64, 3, false>(
        q + ((size_t)i0 * 4 + n) * 256 + h * 32, 1024, 32 * 1024, 524288, 1048576,
        k + ((size_t)j0 * 4 + n) * 256 + h * 32, 1024, 32 * 1024, 524288, 1048576,
        32, smem_u32(smem), tid, wm, wn, lane, acc);

    const int grp = lane >> 2, qid = lane & 3;
#pragma unroll
    for (int fq = 0; fq < 4; fq++)
#pragma unroll
        for (int rr = 0; rr < 2; rr++) {
            int i = i0 + wm + fq * 16 + grp + rr * 8;
            const unsigned char* brow = bkt + ((size_t)n * I_DIM + i) * I_DIM;
            float* orow = out + ((size_t)(h * 4 + n) * I_DIM + i) * I_DIM;
#pragma unroll
            for (int g = 0; g < 8; g++) {
                int j = j0 + wn + g * 8 + qid * 2;
                float2 o;
                o.x = acc[fq][g][rr * 2 + 0] + rel[brow[j + 0] * H_DIM + h];
                o.y = acc[fq][g][rr * 2 + 1] + rel[brow[j + 1] * H_DIM + h];
                *(float2*)(orow + j) = o;
            }
        }
}

// --------- softmax over last dim (512): 1 warp/row, 8 rows/block, no smem -------
__global__ __launch_bounds__(256) void softmax_kernel(
    float* __restrict__ P, __half* __restrict__ Ph) {
    const size_t row = (size_t)blockIdx.x * 8 + (threadIdx.x >> 5);
    const int lane = threadIdx.x & 31;
    float* p = P + row * 512;
    __half* ph = Ph + row * 512;

    float4 xv[4];
#pragma unroll
    for (int it = 0; it < 4; it++) xv[it] = ((float4*)p)[lane + it * 32];

    float m = -1e30f;
#pragma unroll
    for (int it = 0; it < 4; it++)
        m = fmaxf(m, fmaxf(fmaxf(xv[it].x, xv[it].y), fmaxf(xv[it].z, xv[it].w)));
#pragma unroll
    for (int o = 16; o > 0; o >>= 1) m = fmaxf(m, __shfl_xor_sync(0xffffffffu, m, o));

    float s = 0.f;
#pragma unroll
    for (int it = 0; it < 4; it++) {
        xv[it].x = expf(xv[it].x - m); xv[it].y = expf(xv[it].y - m);
        xv[it].z = expf(xv[it].z - m); xv[it].w = expf(xv[it].w - m);
        s += xv[it].x + xv[it].y + xv[it].z + xv[it].w;
    }
#pragma unroll
    for (int o = 16; o > 0; o >>= 1) s += __shfl_xor_sync(0xffffffffu, s, o);
    float inv = 1.0f / s;

#pragma unroll
    for (int it = 0; it < 4; it++) {
        xv[it].x *= inv; xv[it].y *= inv; xv[it].z *= inv; xv[it].w *= inv;
        ((float4*)p)[lane + it * 32] = xv[it];
        __half2 h0 = __float22half2_rn(make_float2(xv[it].x, xv[it].y));
        __half2 h1 = __float22half2_rn(make_float2(xv[it].z, xv[it].w));
        uint2 u; u.x = *(uint32_t*)&h0; u.y = *(uint32_t*)&h1;
        *(uint2*)(ph + (lane + it * 32) * 4) = u;
    }
}

// ===== context: ctx[r,i,n,h,d] = sum_j P[h,n,i,j] v[r,j,n,h,d]  (trans-B) ========
__global__ __launch_bounds__(GT, 2) void context_gemm(
    const __half* __restrict__ Ph, const __half* __restrict__ v,
    __half* __restrict__ ctx)
{
    extern __shared__ __align__(16) char smem[];
    const int tid = threadIdx.x, warp = tid >> 5, lane = tid & 31;
    const int wm = (warp >> 1) * 64, wn = (warp & 1) * 64;
    const int i0 = blockIdx.x * 128;
    const int c0 = blockIdx.y * 128;      // over r*32+d (2048 wide)
    const int r0 = c0 >> 5;               // 4 r values per tile
    const int z = blockIdx.z, h = z >> 2, n = z & 3;
    const int nh = h * 4 + n;

    float acc[4][8][4];
#pragma unroll
    for (int fq = 0; fq < 4; fq++)
#pragma unroll
        for (int g = 0; g < 8; g++)
#pragma unroll
            for (int c = 0; c < 4; c++) acc[fq][g][c] = 0.f;

    gemm_main<32, 4, true>(
        Ph + ((size_t)nh * 512 + i0) * 512, 512, 32 * 512, 0, 32,
        v + ((size_t)r0 * 512 * 4 + n) * 256 + h * 32, 1024, 524288, 0, 32768,
        16, smem_u32(smem), tid, wm, wn, lane, acc);

    const int grp = lane >> 2, qid = lane & 3;
#pragma unroll
    for (int fq = 0; fq < 4; fq++)
#pragma unroll
        for (int rr = 0; rr < 2; rr++) {
            int i = i0 + wm + fq * 16 + grp + rr * 8;
#pragma unroll
            for (int g = 0; g < 8; g++) {
                int col = c0 + wn + g * 8 + qid * 2;
                int r = col >> 5, d = col & 31;
                float2 o;
                o.x = acc[fq][g][rr * 2 + 0];
                o.y = acc[fq][g][rr * 2 + 1];
                *(__half2*)(ctx + (((size_t)r * 512 + i) * 4 + n) * 256 + h * 32 + d) =
                    __float22half2_rn(o);
            }
        }
}

// --------------------------------- launch ---------------------------------------
extern "C" void kernel_launch(void* const* d_in, const int* in_sizes, int n_in,
                              void* d_out, int out_size) {
    const float* x   = (const float*)d_in[0];
    const int*   dst = (const int*)  d_in[1];
    const float* Wq  = (const float*)d_in[2];
    const float* bq  = (const float*)d_in[3];
    const float* Wk  = (const float*)d_in[4];
    const float* bk  = (const float*)d_in[5];
    const float* Wv  = (const float*)d_in[6];
    const float* bv  = (const float*)d_in[7];
    const float* Wo  = (const float*)d_in[8];
    const float* bo  = (const float*)d_in[9];
    const float* rel = (const float*)d_in[10];
    float* out = (float*)d_out;

    __half *xh, *wh, *q, *k, *v, *ctx, *ph;
    float* probs_fallback;
    unsigned char* bkt;
    cudaGetSymbolAddress((void**)&xh,  gh_x);
    cudaGetSymbolAddress((void**)&wh,  gh_w);
    cudaGetSymbolAddress((void**)&q,   gh_q);
    cudaGetSymbolAddress((void**)&k,   gh_k);
    cudaGetSymbolAddress((void**)&v,   gh_v);
    cudaGetSymbolAddress((void**)&ctx, gh_ctx);
    cudaGetSymbolAddress((void**)&ph,  gh_pr);
    cudaGetSymbolAddress((void**)&probs_fallback, g_probs);
    cudaGetSymbolAddress((void**)&bkt, g_bkt);

    float* probs = ((size_t)out_size >= OUT_ELEMS + PROB_ELEMS) ? (out + OUT_ELEMS)
                                                                : probs_fallback;

    cudaFuncSetAttribute(proj_qkv,     cudaFuncAttributeMaxDynamicSharedMemorySize, SM64);
    cudaFuncSetAttribute(proj_out,     cudaFuncAttributeMaxDynamicSharedMemorySize, SM64);
    cudaFuncSetAttribute(logits_gemm,  cudaFuncAttributeMaxDynamicSharedMemorySize, SM64);
    cudaFuncSetAttribute(context_gemm, cudaFuncAttributeMaxDynamicSharedMemorySize, SM32);

    const float scaleq = 0.022097086912079608f;  // D^-0.5 / sqrt(R)
    dim3 blk(256);
    dim3 gblk(GT);

    bucket_kernel<<<(N_DIM * I_DIM * I_DIM) / 256, blk>>>(dst, bkt);

    // fp16 pre-conversion: x and the four 256x256 weights (wh order: Wq,Wk,Wv,Wo)
    conv_f16<<<(int)(OUT_ELEMS / (256 * 8)), blk>>>(x, xh);
    conv_w4<<<dim3(E_DIM * E_DIM / (256 * 8), 4), blk>>>(Wq, Wk, Wv, Wo, wh);

    proj_qkv<<<dim3(T_TOK / 128, E_DIM / 128, 3), gblk, SM64>>>(
        xh, wh, bq, bk, bv, q, k, v, scaleq);

    logits_gemm<<<dim3(I_DIM / 128, I_DIM / 128, N_DIM * H_DIM), gblk, SM64>>>(
        q, k, bkt, rel, probs);
    softmax_kernel<<<(H_DIM * N_DIM * I_DIM) / 8, blk>>>(probs, ph);
    context_gemm<<<dim3(I_DIM / 128, (R_DIM * D_DIM) / 128, N_DIM * H_DIM), gblk, SM32>>>(
        ph, v, ctx);

    proj_out<<<dim3(T_TOK / 128, E_DIM / 128), gblk, SM64>>>(
        ctx, wh + 3 * E_DIM * E_DIM, bo, out);
}

// round 13
// speedup vs baseline: 1.0006x; 1.0006x over previous
#include <cuda_runtime.h>
#include <cuda_fp16.h>
#include <math.h>
#include <stdint.h>

#define R_DIM 64
#define I_DIM 512
#define N_DIM 4
#define E_DIM 256
#define H_DIM 8
#define D_DIM 32
#define T_TOK (R_DIM * I_DIM * N_DIM)                 /* 131072 tokens */
#define OUT_ELEMS ((size_t)T_TOK * E_DIM)             /* 33554432 */
#define PROB_ELEMS ((size_t)H_DIM * N_DIM * I_DIM * I_DIM) /* 8388608 */

// KH=64 path (proj/logits): pitch 144, 3 stages.  KH=32 path (context): pitch 80, 4 stages.
#define SM64 (3 * 2 * 128 * 144)   /* 110592 */
#define SM32 (4 * 2 * 128 * 80)    /*  81920 */

// ---------------- scratch (alloc-free rule: __device__ globals) ----------------
__device__ __half gh_x[T_TOK * E_DIM];
__device__ __half gh_w[4 * E_DIM * E_DIM];
__device__ __half gh_q[T_TOK * E_DIM];
__device__ __half gh_k[T_TOK * E_DIM];
__device__ __half gh_v[T_TOK * E_DIM];
__device__ __half gh_ctx[T_TOK * E_DIM];
__device__ __half gh_pr[PROB_ELEMS];      // fp16 probs for context GEMM
__device__ float g_probs[PROB_ELEMS];     // fallback f32 probs
__device__ unsigned char g_bkt[N_DIM * I_DIM * I_DIM];

// ---------------- low-level helpers ---------------------------------------------
__device__ __forceinline__ uint32_t smem_u32(const void* p) {
    uint32_t a;
    asm("{ .reg .u64 t; cvta.to.shared.u64 t, %1; cvt.u32.u64 %0, t; }" : "=r"(a) : "l"(p));
    return a;
}
__device__ __forceinline__ void cp16(uint32_t saddr, const void* g) {
    asm volatile("cp.async.cg.shared.global [%0], [%1], 16;" :: "r"(saddr), "l"(g));
}
#define CP_COMMIT() asm volatile("cp.async.commit_group;" ::: "memory")
template<int N> __device__ __forceinline__ void cp_wait() {
    if (N == 1) asm volatile("cp.async.wait_group 1;" ::: "memory");
    else        asm volatile("cp.async.wait_group 2;" ::: "memory");
}
__device__ __forceinline__ void ldsm4(uint32_t& r0, uint32_t& r1, uint32_t& r2, uint32_t& r3,
                                      uint32_t addr) {
    asm volatile("ldmatrix.sync.aligned.m8n8.x4.shared.b16 {%0,%1,%2,%3}, [%4];"
                 : "=r"(r0), "=r"(r1), "=r"(r2), "=r"(r3) : "r"(addr));
}
__device__ __forceinline__ void ldsm4t(uint32_t& r0, uint32_t& r1, uint32_t& r2, uint32_t& r3,
                                       uint32_t addr) {
    asm volatile("ldmatrix.sync.aligned.m8n8.x4.trans.shared.b16 {%0,%1,%2,%3}, [%4];"
                 : "=r"(r0), "=r"(r1), "=r"(r2), "=r"(r3) : "r"(addr));
}
__device__ __forceinline__ void mma16816(float c[4], const uint32_t a[4], const uint32_t b[2]) {
    asm volatile(
        "mma.sync.aligned.m16n8k16.row.col.f32.f16.f16.f32 "
        "{%0,%1,%2,%3}, {%4,%5,%6,%7}, {%8,%9}, {%0,%1,%2,%3};"
        : "+f"(c[0]), "+f"(c[1]), "+f"(c[2]), "+f"(c[3])
        : "r"(a[0]), "r"(a[1]), "r"(a[2]), "r"(a[3]), "r"(b[0]), "r"(b[1]));
}

// Tile loader: 128 rows x KH halves via cp.async, 256 threads.
template<int KH>
__device__ __forceinline__ void load_tile(uint32_t sdst, const __half* base,
                                          size_t rowStride, size_t rowGrpStride,
                                          size_t kGrpStride, int tid) {
    constexpr int PITCH = KH * 2 + 16;
    constexpr int NG = KH / 8;
#pragma unroll
    for (int it = 0; it < (128 * NG) / 256; it++) {
        int idx = tid + it * 256;
        int row = idx / NG, g = idx % NG;
        const __half* src = base + (size_t)(row >> 5) * rowGrpStride
                                 + (size_t)(row & 31) * rowStride
                                 + (size_t)(g >> 2) * kGrpStride + (g & 3) * 8;
        cp16(sdst + row * PITCH + g * 16, src);
    }
}

// ---- fragment loads for one k-step (warp tile 64x32) ---------------------------
template<int KH, bool BTRANS>
__device__ __forceinline__ void load_frags(uint32_t aoff, uint32_t boff, int ks,
                                           uint32_t a[4][4], uint32_t b[4][2]) {
    constexpr int PITCH = KH * 2 + 16;
#pragma unroll
    for (int fq = 0; fq < 4; fq++)
        ldsm4(a[fq][0], a[fq][1], a[fq][2], a[fq][3], aoff + fq * (16 * PITCH) + ks * 32);
    if (BTRANS) {
#pragma unroll
        for (int p = 0; p < 2; p++) {
            uint32_t r0, r1, r2, r3;
            ldsm4t(r0, r1, r2, r3, boff + ks * (16 * PITCH) + p * 32);
            b[p * 2][0] = r0; b[p * 2][1] = r1;
            b[p * 2 + 1][0] = r2; b[p * 2 + 1][1] = r3;
        }
    } else {
#pragma unroll
        for (int p = 0; p < 2; p++) {
            uint32_t r0, r1, r2, r3;
            ldsm4(r0, r1, r2, r3, boff + p * (16 * PITCH) + ks * 32);
            b[p * 2][0] = r0; b[p * 2][1] = r1;
            b[p * 2 + 1][0] = r2; b[p * 2 + 1][1] = r3;
        }
    }
}

// --------- per-warp compute on one KH-deep K chunk, frag double-buffered --------
template<int KH, bool BTRANS>
__device__ __forceinline__ void compute_chunk(uint32_t bufA, uint32_t bufB,
                                              int wm, int wn, int lane, float acc[4][4][4]) {
    constexpr int PITCH = KH * 2 + 16;
    constexpr int NK = KH / 16;
    uint32_t aoff = bufA + (uint32_t)((wm + (lane & 15)) * PITCH + ((lane >> 4) << 4));
    uint32_t boff;
    if (BTRANS) {
        boff = bufB + (uint32_t)(((wn >> 5) * 32 + (lane & 15)) * PITCH
                                 + ((lane >> 4) << 4));
    } else {
        boff = bufB + (uint32_t)((wn + ((lane >> 4) << 3) + (lane & 7)) * PITCH
                                 + (((lane >> 3) & 1) << 4));
    }
    uint32_t a[2][4][4];
    uint32_t b[2][4][2];
    load_frags<KH, BTRANS>(aoff, boff, 0, a[0], b[0]);
#pragma unroll
    for (int ks = 0; ks < NK; ks++) {
        int cur = ks & 1;
        if (ks + 1 < NK)
            load_frags<KH, BTRANS>(aoff, boff, ks + 1, a[cur ^ 1], b[cur ^ 1]);
#pragma unroll
        for (int fq = 0; fq < 4; fq++)
#pragma unroll
            for (int g = 0; g < 4; g++)
                mma16816(acc[fq][g], a[cur][fq], b[cur][g]);
    }
}

// NST-stage cp.async mainloop. NCH >= NST-1.
template<int KH, int NST, bool BTRANS>
__device__ __forceinline__ void gemm_main(
    const __half* Ab, size_t rsA, size_t rgA, size_t kgA, size_t chA,
    const __half* Bb, size_t rsB, size_t rgB, size_t kgB, size_t chB,
    int NCH, uint32_t sbase, int tid, int wm, int wn, int lane, float acc[4][4][4])
{
    constexpr int TILEB = 128 * (KH * 2 + 16);
    constexpr int STGB = 2 * TILEB;
#pragma unroll
    for (int s = 0; s < NST - 1; s++) {
        load_tile<KH>(sbase + s * STGB, Ab + (size_t)s * chA, rsA, rgA, kgA, tid);
        load_tile<KH>(sbase + s * STGB + TILEB, Bb + (size_t)s * chB, rsB, rgB, kgB, tid);
        CP_COMMIT();
    }
    int cs = 0, ls = NST - 1;
    for (int ch = 0; ch < NCH; ch++) {
        cp_wait<NST - 2>();
        __syncthreads();
        if (ch + NST - 1 < NCH) {
            uint32_t so = sbase + ls * STGB;
            load_tile<KH>(so, Ab + (size_t)(ch + NST - 1) * chA, rsA, rgA, kgA, tid);
            load_tile<KH>(so + TILEB, Bb + (size_t)(ch + NST - 1) * chB, rsB, rgB, kgB, tid);
        }
        CP_COMMIT();
        if (++ls == NST) ls = 0;
        compute_chunk<KH, BTRANS>(sbase + cs * STGB, sbase + cs * STGB + TILEB,
                                  wm, wn, lane, acc);
        if (++cs == NST) cs = 0;
    }
}

// T5 bucketize (verified exact vs jnp.linspace/searchsorted in R2/R3)
__device__ __forceinline__ int bucket_of(int dist) {
    int ad = dist < 0 ? -dist : dist;
    float v = (float)ad;
    int lo = 0, hi = 62;
#pragma unroll
    for (int it = 0; it < 6; it++) {
        int mid = (lo + hi) >> 1;
        float b = (float)((50000.0 * (double)mid) / 62.0);
        if (b >= v) hi = mid; else lo = mid + 1;
    }
    return lo;
}
__global__ __launch_bounds__(256) void bucket_kernel(
    const int* __restrict__ dist, unsigned char* __restrict__ bkt) {
    int idx = blockIdx.x * 256 + threadIdx.x;
    bkt[idx] = (unsigned char)bucket_of(dist[idx]);
}

// ---------------- f32 -> f16 bulk converts --------------------------------------
__global__ __launch_bounds__(256) void conv_f16(
    const float* __restrict__ src, __half* __restrict__ dst) {
    size_t idx = ((size_t)blockIdx.x * 256 + threadIdx.x) * 8;
    float4 a = *(const float4*)(src + idx);
    float4 b = *(const float4*)(src + idx + 4);
    __half2 h0 = __float22half2_rn(make_float2(a.x, a.y));
    __half2 h1 = __float22half2_rn(make_float2(a.z, a.w));
    __half2 h2 = __float22half2_rn(make_float2(b.x, b.y));
    __half2 h3 = __float22half2_rn(make_float2(b.z, b.w));
    uint4 u;
    u.x = *(uint32_t*)&h0; u.y = *(uint32_t*)&h1;
    u.z = *(uint32_t*)&h2; u.w = *(uint32_t*)&h3;
    *(uint4*)(dst + idx) = u;
}
__global__ __launch_bounds__(256) void conv_w4(
    const float* __restrict__ w0, const float* __restrict__ w1,
    const float* __restrict__ w2, const float* __restrict__ w3,
    __half* __restrict__ dst) {
    const float* src = (blockIdx.y == 0) ? w0 : (blockIdx.y == 1) ? w1
                      : (blockIdx.y == 2) ? w2 : w3;
    size_t idx = ((size_t)blockIdx.x * 256 + threadIdx.x) * 8;
    float4 a = *(const float4*)(src + idx);
    float4 b = *(const float4*)(src + idx + 4);
    __half2 h0 = __float22half2_rn(make_float2(a.x, a.y));
    __half2 h1 = __float22half2_rn(make_float2(a.z, a.w));
    __half2 h2 = __float22half2_rn(make_float2(b.x, b.y));
    __half2 h3 = __float22half2_rn(make_float2(b.z, b.w));
    uint4 u;
    u.x = *(uint32_t*)&h0; u.y = *(uint32_t*)&h1;
    u.z = *(uint32_t*)&h2; u.w = *(uint32_t*)&h3;
    *(uint4*)(dst + (size_t)blockIdx.y * E_DIM * E_DIM + idx) = u;
}

// ============ fused QKV projection: z selects (W, bias, out, scale) =============
__global__ __launch_bounds__(256, 2) void proj_qkv(
    const __half* __restrict__ A, const __half* __restrict__ Wall,
    const float* __restrict__ bq, const float* __restrict__ bk,
    const float* __restrict__ bv,
    __half* __restrict__ oq, __half* __restrict__ ok, __half* __restrict__ ov,
    float scaleq)
{
    extern __shared__ __align__(16) char smem[];
    const int tid = threadIdx.x, warp = tid >> 5, lane = tid & 31;
    const int wm = (warp >> 2) * 64, wn = (warp & 3) * 32;
    const int t0 = blockIdx.x * 128, f0 = blockIdx.y * 128;
    const int z = blockIdx.z;
    const __half* W = Wall + (size_t)z * E_DIM * E_DIM;
    const float* bias = (z == 0) ? bq : (z == 1) ? bk : bv;
    __half* C = (z == 0) ? oq : (z == 1) ? ok : ov;
    const float scale = (z == 0) ? scaleq : 1.0f;

    float acc[4][4][4];
#pragma unroll
    for (int fq = 0; fq < 4; fq++)
#pragma unroll
        for (int g = 0; g < 4; g++)
#pragma unroll
            for (int c = 0; c < 4; c++) acc[fq][g][c] = 0.f;

    gemm_main<64, 3, false>(
        A + (size_t)t0 * E_DIM, E_DIM, 32 * E_DIM, 32, 64,
        W + (size_t)f0 * E_DIM, E_DIM, 32 * E_DIM, 32, 64,
        E_DIM / 64, smem_u32(smem), tid, wm, wn, lane, acc);

    const int grp = lane >> 2, qid = lane & 3;
#pragma unroll
    for (int fq = 0; fq < 4; fq++)
#pragma unroll
        for (int rr = 0; rr < 2; rr++) {
            int i = t0 + wm + fq * 16 + grp + rr * 8;
#pragma unroll
            for (int g = 0; g < 4; g++) {
                int col = f0 + wn + g * 8 + qid * 2;
                float2 o;
                o.x = (acc[fq][g][rr * 2 + 0] + bias[col + 0]) * scale;
                o.y = (acc[fq][g][rr * 2 + 1] + bias[col + 1]) * scale;
                *(__half2*)(C + (size_t)i * E_DIM + col) = __float22half2_rn(o);
            }
        }
}

// ===================== output projection: f16 in, f32 out =======================
__global__ __launch_bounds__(256, 2) void proj_out(
    const __half* __restrict__ A, const __half* __restrict__ W,
    const float* __restrict__ bias, float* __restrict__ C)
{
    extern __shared__ __align__(16) char smem[];
    const int tid = threadIdx.x, warp = tid >> 5, lane = tid & 31;
    const int wm = (warp >> 2) * 64, wn = (warp & 3) * 32;
    const int t0 = blockIdx.x * 128, f0 = blockIdx.y * 128;

    float acc[4][4][4];
#pragma unroll
    for (int fq = 0; fq < 4; fq++)
#pragma unroll
        for (int g = 0; g < 4; g++)
#pragma unroll
            for (int c = 0; c < 4; c++) acc[fq][g][c] = 0.f;

    gemm_main<64, 3, false>(
        A + (size_t)t0 * E_DIM, E_DIM, 32 * E_DIM, 32, 64,
        W + (size_t)f0 * E_DIM, E_DIM, 32 * E_DIM, 32, 64,
        E_DIM / 64, smem_u32(smem), tid, wm, wn, lane, acc);

    const int grp = lane >> 2, qid = lane & 3;
#pragma unroll
    for (int fq = 0; fq < 4; fq++)
#pragma unroll
        for (int rr = 0; rr < 2; rr++) {
            int i = t0 + wm + fq * 16 + grp + rr * 8;
#pragma unroll
            for (int g = 0; g < 4; g++) {
                int col = f0 + wn + g * 8 + qid * 2;
                float2 o;
                o.x = acc[fq][g][rr * 2 + 0] + bias[col + 0];
                o.y = acc[fq][g][rr * 2 + 1] + bias[col + 1];
                *(float2*)(C + (size_t)i * E_DIM + col) = o;
            }
        }
}

// =========== logits: out[h,n,i,j] = sum_{r,d} q·k + rel[bucket[n,i,j],h] =========
__global__ __launch_bounds__(256, 2) void logits_gemm(
    const __half* __restrict__ q, const __half* __restrict__ k,
    const unsigned char* __restrict__ bkt, const float* __restrict__ rel,
    float* __restrict__ out)
{
    extern __shared__ __align__(16) char smem[];
    const int tid = threadIdx.x, warp = tid >> 5, lane = tid & 31;
    const int wm = (warp >> 2) * 64, wn = (warp & 3) * 32;
    const int i0 = blockIdx.x * 128, j0 = blockIdx.y * 128;
    const int z = blockIdx.z, h = z >> 2, n = z & 3;

    float acc[4][4][4];
#pragma unroll
    for (int fq = 0; fq < 4; fq++)
#pragma unroll
        for (int g = 0; g < 4; g++)
#pragma unroll
            for (int c = 0; c < 4; c++) acc[fq][g][c] = 0.f;

    // K chunk = 2 r values: [r0 d0..31 | r1 d0..31]; same packing both operands.
    gemm_main<64, 3, false>(
        q + ((size_t)i0 * 4 + n) * 256 + h * 32, 1024, 32 * 1024, 524288, 1048576,
        k + ((size_t)j0 * 4 + n) * 256 + h * 32, 1024, 32 * 1024, 524288, 1048576,
        32, smem_u32(smem), tid, wm, wn, lane, acc);

    const int grp = lane >> 2, qid = lane & 3;
#pragma unroll
    for (int fq = 0; fq < 4; fq++)
#pragma unroll
        for (int rr = 0; rr < 2; rr++) {
            int i = i0 + wm + fq * 16 + grp + rr * 8;
            const unsigned char* brow = bkt + ((size_t)n * I_DIM + i) * I_DIM;
            float* orow = out + ((size_t)(h * 4 + n) * I_DIM + i) * I_DIM;
#pragma unroll
            for (int g = 0; g < 4; g++) {
                int j = j0 + wn + g * 8 + qid * 2;
                float2 o;
                o.x = acc[fq][g][rr * 2 + 0] + rel[brow[j + 0] * H_DIM + h];
                o.y = acc[fq][g][rr * 2 + 1] + rel[brow[j + 1] * H_DIM + h];
                *(float2*)(orow + j) = o;
            }
        }
}

// --------- softmax over last dim (512): 1 warp/row, 8 rows/block, no smem -------
__global__ __launch_bounds__(256) void softmax_kernel(
    float* __restrict__ P, __half* __restrict__ Ph) {
    const size_t row = (size_t)blockIdx.x * 8 + (threadIdx.x >> 5);
    const int lane = threadIdx.x & 31;
    float* p = P + row * 512;
    __half* ph = Ph + row * 512;

    float4 xv[4];
#pragma unroll
    for (int it = 0; it < 4; it++) xv[it] = ((float4*)p)[lane + it * 32];

    float m = -1e30f;
#pragma unroll
    for (int it = 0; it < 4; it++)
        m = fmaxf(m, fmaxf(fmaxf(xv[it].x, xv[it].y), fmaxf(xv[it].z, xv[it].w)));
#pragma unroll
    for (int o = 16; o > 0; o >>= 1) m = fmaxf(m, __shfl_xor_sync(0xffffffffu, m, o));

    float s = 0.f;
#pragma unroll
    for (int it = 0; it < 4; it++) {
        xv[it].x = expf(xv[it].x - m); xv[it].y = expf(xv[it].y - m);
        xv[it].z = expf(xv[it].z - m); xv[it].w = expf(xv[it].w - m);
        s += xv[it].x + xv[it].y + xv[it].z + xv[it].w;
    }
#pragma unroll
    for (int o = 16; o > 0; o >>= 1) s += __shfl_xor_sync(0xffffffffu, s, o);
    float inv = 1.0f / s;

#pragma unroll
    for (int it = 0; it < 4; it++) {
        xv[it].x *= inv; xv[it].y *= inv; xv[it].z *= inv; xv[it].w *= inv;
        ((float4*)p)[lane + it * 32] = xv[it];
        __half2 h0 = __float22half2_rn(make_float2(xv[it].x, xv[it].y));
        __half2 h1 = __float22half2_rn(make_float2(xv[it].z, xv[it].w));
        uint2 u; u.x = *(uint32_t*)&h0; u.y = *(uint32_t*)&h1;
        *(uint2*)(ph + (lane + it * 32) * 4) = u;
    }
}

// ===== context: ctx[r,i,n,h,d] = sum_j P[h,n,i,j] v[r,j,n,h,d]  (trans-B) ========
__global__ __launch_bounds__(256, 2) void context_gemm(
    const __half* __restrict__ Ph, const __half* __restrict__ v,
    __half* __restrict__ ctx)
{
    extern __shared__ __align__(16) char smem[];
    const int tid = threadIdx.x, warp = tid >> 5, lane = tid & 31;
    const int wm = (warp >> 2) * 64, wn = (warp & 3) * 32;
    const int i0 = blockIdx.x * 128;
    const int c0 = blockIdx.y * 128;      // over r*32+d (2048 wide)
    const int r0 = c0 >> 5;               // 4 r values per tile
    const int z = blockIdx.z, h = z >> 2, n = z & 3;
    const int nh = h * 4 + n;

    float acc[4][4][4];
#pragma unroll
    for (int fq = 0; fq < 4; fq++)
#pragma unroll
        for (int g = 0; g < 4; g++)
#pragma unroll
            for (int c = 0; c < 4; c++) acc[fq][g][c] = 0.f;

    gemm_main<32, 4, true>(
        Ph + ((size_t)nh * 512 + i0) * 512, 512, 32 * 512, 0, 32,
        v + ((size_t)r0 * 512 * 4 + n) * 256 + h * 32, 1024, 524288, 0, 32768,
        16, smem_u32(smem), tid, wm, wn, lane, acc);

    const int grp = lane >> 2, qid = lane & 3;
#pragma unroll
    for (int fq = 0; fq < 4; fq++)
#pragma unroll
        for (int rr = 0; rr < 2; rr++) {
            int i = i0 + wm + fq * 16 + grp + rr * 8;
#pragma unroll
            for (int g = 0; g < 4; g++) {
                int col = c0 + wn + g * 8 + qid * 2;
                int r = col >> 5, d = col & 31;
                float2 o;
                o.x = acc[fq][g][rr * 2 + 0];
                o.y = acc[fq][g][rr * 2 + 1];
                *(__half2*)(ctx + (((size_t)r * 512 + i) * 4 + n) * 256 + h * 32 + d) =
                    __float22half2_rn(o);
            }
        }
}

// --------------------------------- launch ---------------------------------------
extern "C" void kernel_launch(void* const* d_in, const int* in_sizes, int n_in,
                              void* d_out, int out_size) {
    const float* x   = (const float*)d_in[0];
    const int*   dst = (const int*)  d_in[1];
    const float* Wq  = (const float*)d_in[2];
    const float* bq  = (const float*)d_in[3];
    const float* Wk  = (const float*)d_in[4];
    const float* bk  = (const float*)d_in[5];
    const float* Wv  = (const float*)d_in[6];
    const float* bv  = (const float*)d_in[7];
    const float* Wo  = (const float*)d_in[8];
    const float* bo  = (const float*)d_in[9];
    const float* rel = (const float*)d_in[10];
    float* out = (float*)d_out;

    __half *xh, *wh, *q, *k, *v, *ctx, *ph;
    float* probs_fallback;
    unsigned char* bkt;
    cudaGetSymbolAddress((void**)&xh,  gh_x);
    cudaGetSymbolAddress((void**)&wh,  gh_w);
    cudaGetSymbolAddress((void**)&q,   gh_q);
    cudaGetSymbolAddress((void**)&k,   gh_k);
    cudaGetSymbolAddress((void**)&v,   gh_v);
    cudaGetSymbolAddress((void**)&ctx, gh_ctx);
    cudaGetSymbolAddress((void**)&ph,  gh_pr);
    cudaGetSymbolAddress((void**)&probs_fallback, g_probs);
    cudaGetSymbolAddress((void**)&bkt, g_bkt);

    float* probs = ((size_t)out_size >= OUT_ELEMS + PROB_ELEMS) ? (out + OUT_ELEMS)
                                                                : probs_fallback;

    cudaFuncSetAttribute(proj_qkv,     cudaFuncAttributeMaxDynamicSharedMemorySize, SM64);
    cudaFuncSetAttribute(proj_out,     cudaFuncAttributeMaxDynamicSharedMemorySize, SM64);
    cudaFuncSetAttribute(logits_gemm,  cudaFuncAttributeMaxDynamicSharedMemorySize, SM64);
    cudaFuncSetAttribute(context_gemm, cudaFuncAttributeMaxDynamicSharedMemorySize, SM32);

    const float scaleq = 0.022097086912079608f;  // D^-0.5 / sqrt(R)
    dim3 blk(256);

    bucket_kernel<<<(N_DIM * I_DIM * I_DIM) / 256, blk>>>(dst, bkt);

    // fp16 pre-conversion: x and the four 256x256 weights (wh order: Wq,Wk,Wv,Wo)
    conv_f16<<<(int)(OUT_ELEMS / (256 * 8)), blk>>>(x, xh);
    conv_w4<<<dim3(E_DIM * E_DIM / (256 * 8), 4), blk>>>(Wq, Wk, Wv, Wo, wh);

    proj_qkv<<<dim3(T_TOK / 128, E_DIM / 128, 3), blk, SM64>>>(
        xh, wh, bq, bk, bv, q, k, v, scaleq);

    logits_gemm<<<dim3(I_DIM / 128, I_DIM / 128, N_DIM * H_DIM), blk, SM64>>>(
        q, k, bkt, rel, probs);
    softmax_kernel<<<(H_DIM * N_DIM * I_DIM) / 8, blk>>>(probs, ph);
    context_gemm<<<dim3(I_DIM / 128, (R_DIM * D_DIM) / 128, N_DIM * H_DIM), blk, SM32>>>(
        ph, v, ctx);

    proj_out<<<dim3(T_TOK / 128, E_DIM / 128), blk, SM64>>>(
        ctx, wh + 3 * E_DIM * E_DIM, bo, out);
}

// round 14
// speedup vs baseline: 1.0138x; 1.0131x over previous
#include <cuda_runtime.h>
#include <cuda_fp16.h>
#include <math.h>
#include <stdint.h>

#define R_DIM 64
#define I_DIM 512
#define N_DIM 4
#define E_DIM 256
#define H_DIM 8
#define D_DIM 32
#define T_TOK (R_DIM * I_DIM * N_DIM)                 /* 131072 tokens */
#define OUT_ELEMS ((size_t)T_TOK * E_DIM)             /* 33554432 */
#define PROB_ELEMS ((size_t)H_DIM * N_DIM * I_DIM * I_DIM) /* 8388608 */

// KH=64 path (proj/logits): pitch 144, 3 stages.  KH=32 path (context): pitch 80, 5 stages.
#define SM64 (3 * 2 * 128 * 144)   /* 110592 */
#define SM32 (5 * 2 * 128 * 80)    /* 102400 */

// ---------------- scratch (alloc-free rule: __device__ globals) ----------------
__device__ __half gh_x[T_TOK * E_DIM];
__device__ __half gh_w[4 * E_DIM * E_DIM];
__device__ __half gh_q[T_TOK * E_DIM];
__device__ __half gh_k[T_TOK * E_DIM];
__device__ __half gh_v[T_TOK * E_DIM];
__device__ __half gh_ctx[T_TOK * E_DIM];
__device__ __half gh_pr[PROB_ELEMS];      // fp16 probs for context GEMM
__device__ float g_probs[PROB_ELEMS];     // fallback f32 probs
__device__ unsigned char g_bkt[N_DIM * I_DIM * I_DIM];

// ---------------- low-level helpers ---------------------------------------------
__device__ __forceinline__ uint32_t smem_u32(const void* p) {
    uint32_t a;
    asm("{ .reg .u64 t; cvta.to.shared.u64 t, %1; cvt.u32.u64 %0, t; }" : "=r"(a) : "l"(p));
    return a;
}
__device__ __forceinline__ void cp16(uint32_t saddr, const void* g) {
    asm volatile("cp.async.cg.shared.global [%0], [%1], 16;" :: "r"(saddr), "l"(g));
}
#define CP_COMMIT() asm volatile("cp.async.commit_group;" ::: "memory")
template<int N> __device__ __forceinline__ void cp_wait() {
    if (N == 1)      asm volatile("cp.async.wait_group 1;" ::: "memory");
    else if (N == 2) asm volatile("cp.async.wait_group 2;" ::: "memory");
    else             asm volatile("cp.async.wait_group 3;" ::: "memory");
}
__device__ __forceinline__ void ldsm4(uint32_t& r0, uint32_t& r1, uint32_t& r2, uint32_t& r3,
                                      uint32_t addr) {
    asm volatile("ldmatrix.sync.aligned.m8n8.x4.shared.b16 {%0,%1,%2,%3}, [%4];"
                 : "=r"(r0), "=r"(r1), "=r"(r2), "=r"(r3) : "r"(addr));
}
__device__ __forceinline__ void ldsm4t(uint32_t& r0, uint32_t& r1, uint32_t& r2, uint32_t& r3,
                                       uint32_t addr) {
    asm volatile("ldmatrix.sync.aligned.m8n8.x4.trans.shared.b16 {%0,%1,%2,%3}, [%4];"
                 : "=r"(r0), "=r"(r1), "=r"(r2), "=r"(r3) : "r"(addr));
}
__device__ __forceinline__ void mma16816(float c[4], const uint32_t a[4], const uint32_t b[2]) {
    asm volatile(
        "mma.sync.aligned.m16n8k16.row.col.f32.f16.f16.f32 "
        "{%0,%1,%2,%3}, {%4,%5,%6,%7}, {%8,%9}, {%0,%1,%2,%3};"
        : "+f"(c[0]), "+f"(c[1]), "+f"(c[2]), "+f"(c[3])
        : "r"(a[0]), "r"(a[1]), "r"(a[2]), "r"(a[3]), "r"(b[0]), "r"(b[1]));
}

// Tile loader: 128 rows x KH halves via cp.async, 256 threads.
template<int KH>
__device__ __forceinline__ void load_tile(uint32_t sdst, const __half* base,
                                          size_t rowStride, size_t rowGrpStride,
                                          size_t kGrpStride, int tid) {
    constexpr int PITCH = KH * 2 + 16;
    constexpr int NG = KH / 8;
#pragma unroll
    for (int it = 0; it < (128 * NG) / 256; it++) {
        int idx = tid + it * 256;
        int row = idx / NG, g = idx % NG;
        const __half* src = base + (size_t)(row >> 5) * rowGrpStride
                                 + (size_t)(row & 31) * rowStride
                                 + (size_t)(g >> 2) * kGrpStride + (g & 3) * 8;
        cp16(sdst + row * PITCH + g * 16, src);
    }
}

// --------- per-warp compute on one KH-deep K chunk (warp tile 64x32) ------------
template<int KH, bool BTRANS>
__device__ __forceinline__ void compute_chunk(uint32_t bufA, uint32_t bufB,
                                              int wm, int wn, int lane, float acc[4][4][4]) {
    constexpr int PITCH = KH * 2 + 16;
    uint32_t aoff = bufA + (uint32_t)((wm + (lane & 15)) * PITCH + ((lane >> 4) << 4));
    uint32_t boff;
    if (BTRANS) {
        boff = bufB + (uint32_t)(((wn >> 5) * 32 + (lane & 15)) * PITCH
                                 + ((lane >> 4) << 4));
    } else {
        boff = bufB + (uint32_t)((wn + ((lane >> 4) << 3) + (lane & 7)) * PITCH
                                 + (((lane >> 3) & 1) << 4));
    }
#pragma unroll
    for (int ks = 0; ks < KH / 16; ks++) {
        uint32_t a[4][4];
#pragma unroll
        for (int fq = 0; fq < 4; fq++)
            ldsm4(a[fq][0], a[fq][1], a[fq][2], a[fq][3], aoff + fq * (16 * PITCH) + ks * 32);
        uint32_t b[4][2];
        if (BTRANS) {
#pragma unroll
            for (int p = 0; p < 2; p++) {
                uint32_t r0, r1, r2, r3;
                ldsm4t(r0, r1, r2, r3, boff + ks * (16 * PITCH) + p * 32);
                b[p * 2][0] = r0; b[p * 2][1] = r1;
                b[p * 2 + 1][0] = r2; b[p * 2 + 1][1] = r3;
            }
        } else {
#pragma unroll
            for (int p = 0; p < 2; p++) {
                uint32_t r0, r1, r2, r3;
                ldsm4(r0, r1, r2, r3, boff + p * (16 * PITCH) + ks * 32);
                b[p * 2][0] = r0; b[p * 2][1] = r1;
                b[p * 2 + 1][0] = r2; b[p * 2 + 1][1] = r3;
            }
        }
#pragma unroll
        for (int fq = 0; fq < 4; fq++)
#pragma unroll
            for (int g = 0; g < 4; g++)
                mma16816(acc[fq][g], a[fq], b[g]);
    }
}

// NST-stage cp.async mainloop. NCH >= NST-1.
template<int KH, int NST, bool BTRANS>
__device__ __forceinline__ void gemm_main(
    const __half* Ab, size_t rsA, size_t rgA, size_t kgA, size_t chA,
    const __half* Bb, size_t rsB, size_t rgB, size_t kgB, size_t chB,
    int NCH, uint32_t sbase, int tid, int wm, int wn, int lane, float acc[4][4][4])
{
    constexpr int TILEB = 128 * (KH * 2 + 16);
    constexpr int STGB = 2 * TILEB;
#pragma unroll
    for (int s = 0; s < NST - 1; s++) {
        load_tile<KH>(sbase + s * STGB, Ab + (size_t)s * chA, rsA, rgA, kgA, tid);
        load_tile<KH>(sbase + s * STGB + TILEB, Bb + (size_t)s * chB, rsB, rgB, kgB, tid);
        CP_COMMIT();
    }
    int cs = 0, ls = NST - 1;
    for (int ch = 0; ch < NCH; ch++) {
        cp_wait<NST - 2>();
        __syncthreads();
        if (ch + NST - 1 < NCH) {
            uint32_t so = sbase + ls * STGB;
            load_tile<KH>(so, Ab + (size_t)(ch + NST - 1) * chA, rsA, rgA, kgA, tid);
            load_tile<KH>(so + TILEB, Bb + (size_t)(ch + NST - 1) * chB, rsB, rgB, kgB, tid);
        }
        CP_COMMIT();
        if (++ls == NST) ls = 0;
        compute_chunk<KH, BTRANS>(sbase + cs * STGB, sbase + cs * STGB + TILEB,
                                  wm, wn, lane, acc);
        if (++cs == NST) cs = 0;
    }
}

// T5 bucketize (verified exact vs jnp.linspace/searchsorted in R2/R3)
__device__ __forceinline__ int bucket_of(int dist) {
    int ad = dist < 0 ? -dist : dist;
    float v = (float)ad;
    int lo = 0, hi = 62;
#pragma unroll
    for (int it = 0; it < 6; it++) {
        int mid = (lo + hi) >> 1;
        float b = (float)((50000.0 * (double)mid) / 62.0);
        if (b >= v) hi = mid; else lo = mid + 1;
    }
    return lo;
}

// ------------- fused prep: x->f16, W*4->f16, bucketize (one launch) -------------
// grid.x = XBLK + WBLK + BBLK
#define XBLK (T_TOK * E_DIM / 2048)          /* 16384: x convert, 8 f32/thread */
#define WBLK (4 * E_DIM * E_DIM / 2048)      /* 128: W convert */
#define BBLK (N_DIM * I_DIM * I_DIM / 256)   /* 4096: bucketize */
__global__ __launch_bounds__(256) void prep_kernel(
    const float* __restrict__ x, __half* __restrict__ xh,
    const float* __restrict__ w0, const float* __restrict__ w1,
    const float* __restrict__ w2, const float* __restrict__ w3,
    __half* __restrict__ wh,
    const int* __restrict__ dist, unsigned char* __restrict__ bkt)
{
    int b = blockIdx.x;
    if (b < XBLK + WBLK) {
        const float* src;
        __half* dst;
        if (b < XBLK) {
            src = x; dst = xh;
        } else {
            int wb = b - XBLK;              // 32 blocks per W matrix
            int wi = wb >> 5;
            src = (wi == 0) ? w0 : (wi == 1) ? w1 : (wi == 2) ? w2 : w3;
            dst = wh + (size_t)wi * E_DIM * E_DIM;
            b = XBLK + (wb & 31);           // local block within this W
            src -= (size_t)(XBLK + (wb & 31)) * 2048 - (size_t)(wb & 31) * 2048; // normalize below
            src = ((wi == 0) ? w0 : (wi == 1) ? w1 : (wi == 2) ? w2 : w3);
            size_t idx = ((size_t)(wb & 31) * 256 + threadIdx.x) * 8;
            float4 a = *(const float4*)(src + idx);
            float4 c = *(const float4*)(src + idx + 4);
            __half2 h0 = __float22half2_rn(make_float2(a.x, a.y));
            __half2 h1 = __float22half2_rn(make_float2(a.z, a.w));
            __half2 h2 = __float22half2_rn(make_float2(c.x, c.y));
            __half2 h3 = __float22half2_rn(make_float2(c.z, c.w));
            uint4 u;
            u.x = *(uint32_t*)&h0; u.y = *(uint32_t*)&h1;
            u.z = *(uint32_t*)&h2; u.w = *(uint32_t*)&h3;
            *(uint4*)(dst + idx) = u;
            return;
        }
        size_t idx = ((size_t)b * 256 + threadIdx.x) * 8;
        float4 a = *(const float4*)(src + idx);
        float4 c = *(const float4*)(src + idx + 4);
        __half2 h0 = __float22half2_rn(make_float2(a.x, a.y));
        __half2 h1 = __float22half2_rn(make_float2(a.z, a.w));
        __half2 h2 = __float22half2_rn(make_float2(c.x, c.y));
        __half2 h3 = __float22half2_rn(make_float2(c.z, c.w));
        uint4 u;
        u.x = *(uint32_t*)&h0; u.y = *(uint32_t*)&h1;
        u.z = *(uint32_t*)&h2; u.w = *(uint32_t*)&h3;
        *(uint4*)(dst + idx) = u;
    } else {
        int bb = b - XBLK - WBLK;
        int idx = bb * 256 + threadIdx.x;
        bkt[idx] = (unsigned char)bucket_of(dist[idx]);
    }
}

// ============ fused QKV projection: z selects (W, bias, out, scale) =============
__global__ __launch_bounds__(256, 2) void proj_qkv(
    const __half* __restrict__ A, const __half* __restrict__ Wall,
    const float* __restrict__ bq, const float* __restrict__ bk,
    const float* __restrict__ bv,
    __half* __restrict__ oq, __half* __restrict__ ok, __half* __restrict__ ov,
    float scaleq)
{
    extern __shared__ __align__(16) char smem[];
    const int tid = threadIdx.x, warp = tid >> 5, lane = tid & 31;
    const int wm = (warp >> 2) * 64, wn = (warp & 3) * 32;
    const int t0 = blockIdx.x * 128, f0 = blockIdx.y * 128;
    const int z = blockIdx.z;
    const __half* W = Wall + (size_t)z * E_DIM * E_DIM;
    const float* bias = (z == 0) ? bq : (z == 1) ? bk : bv;
    __half* C = (z == 0) ? oq : (z == 1) ? ok : ov;
    const float scale = (z == 0) ? scaleq : 1.0f;

    float acc[4][4][4];
#pragma unroll
    for (int fq = 0; fq < 4; fq++)
#pragma unroll
        for (int g = 0; g < 4; g++)
#pragma unroll
            for (int c = 0; c < 4; c++) acc[fq][g][c] = 0.f;

    gemm_main<64, 3, false>(
        A + (size_t)t0 * E_DIM, E_DIM, 32 * E_DIM, 32, 64,
        W + (size_t)f0 * E_DIM, E_DIM, 32 * E_DIM, 32, 64,
        E_DIM / 64, smem_u32(smem), tid, wm, wn, lane, acc);

    const int grp = lane >> 2, qid = lane & 3;
#pragma unroll
    for (int fq = 0; fq < 4; fq++)
#pragma unroll
        for (int rr = 0; rr < 2; rr++) {
            int i = t0 + wm + fq * 16 + grp + rr * 8;
#pragma unroll
            for (int g = 0; g < 4; g++) {
                int col = f0 + wn + g * 8 + qid * 2;
                float2 o;
                o.x = (acc[fq][g][rr * 2 + 0] + bias[col + 0]) * scale;
                o.y = (acc[fq][g][rr * 2 + 1] + bias[col + 1]) * scale;
                *(__half2*)(C + (size_t)i * E_DIM + col) = __float22half2_rn(o);
            }
        }
}

// ===================== output projection: f16 in, f32 out =======================
__global__ __launch_bounds__(256, 2) void proj_out(
    const __half* __restrict__ A, const __half* __restrict__ W,
    const float* __restrict__ bias, float* __restrict__ C)
{
    extern __shared__ __align__(16) char smem[];
    const int tid = threadIdx.x, warp = tid >> 5, lane = tid & 31;
    const int wm = (warp >> 2) * 64, wn = (warp & 3) * 32;
    const int t0 = blockIdx.x * 128, f0 = blockIdx.y * 128;

    float acc[4][4][4];
#pragma unroll
    for (int fq = 0; fq < 4; fq++)
#pragma unroll
        for (int g = 0; g < 4; g++)
#pragma unroll
            for (int c = 0; c < 4; c++) acc[fq][g][c] = 0.f;

    gemm_main<64, 3, false>(
        A + (size_t)t0 * E_DIM, E_DIM, 32 * E_DIM, 32, 64,
        W + (size_t)f0 * E_DIM, E_DIM, 32 * E_DIM, 32, 64,
        E_DIM / 64, smem_u32(smem), tid, wm, wn, lane, acc);

    const int grp = lane >> 2, qid = lane & 3;
#pragma unroll
    for (int fq = 0; fq < 4; fq++)
#pragma unroll
        for (int rr = 0; rr < 2; rr++) {
            int i = t0 + wm + fq * 16 + grp + rr * 8;
#pragma unroll
            for (int g = 0; g < 4; g++) {
                int col = f0 + wn + g * 8 + qid * 2;
                float2 o;
                o.x = acc[fq][g][rr * 2 + 0] + bias[col + 0];
                o.y = acc[fq][g][rr * 2 + 1] + bias[col + 1];
                *(float2*)(C + (size_t)i * E_DIM + col) = o;
            }
        }
}

// =========== logits: out[h,n,i,j] = sum_{r,d} q·k + rel[bucket[n,i,j],h] =========
__global__ __launch_bounds__(256, 2) void logits_gemm(
    const __half* __restrict__ q, const __half* __restrict__ k,
    const unsigned char* __restrict__ bkt, const float* __restrict__ rel,
    float* __restrict__ out)
{
    extern __shared__ __align__(16) char smem[];
    const int tid = threadIdx.x, warp = tid >> 5, lane = tid & 31;
    const int wm = (warp >> 2) * 64, wn = (warp & 3) * 32;
    const int i0 = blockIdx.x * 128, j0 = blockIdx.y * 128;
    const int z = blockIdx.z, h = z >> 2, n = z & 3;

    float acc[4][4][4];
#pragma unroll
    for (int fq = 0; fq < 4; fq++)
#pragma unroll
        for (int g = 0; g < 4; g++)
#pragma unroll
            for (int c = 0; c < 4; c++) acc[fq][g][c] = 0.f;

    // K chunk = 2 r values: [r0 d0..31 | r1 d0..31]; same packing both operands.
    gemm_main<64, 3, false>(
        q + ((size_t)i0 * 4 + n) * 256 + h * 32, 1024, 32 * 1024, 524288, 1048576,
        k + ((size_t)j0 * 4 + n) * 256 + h * 32, 1024, 32 * 1024, 524288, 1048576,
        32, smem_u32(smem), tid, wm, wn, lane, acc);

    const int grp = lane >> 2, qid = lane & 3;
#pragma unroll
    for (int fq = 0; fq < 4; fq++)
#pragma unroll
        for (int rr = 0; rr < 2; rr++) {
            int i = i0 + wm + fq * 16 + grp + rr * 8;
            const unsigned char* brow = bkt + ((size_t)n * I_DIM + i) * I_DIM;
            float* orow = out + ((size_t)(h * 4 + n) * I_DIM + i) * I_DIM;
#pragma unroll
            for (int g = 0; g < 4; g++) {
                int j = j0 + wn + g * 8 + qid * 2;
                float2 o;
                o.x = acc[fq][g][rr * 2 + 0] + rel[brow[j + 0] * H_DIM + h];
                o.y = acc[fq][g][rr * 2 + 1] + rel[brow[j + 1] * H_DIM + h];
                *(float2*)(orow + j) = o;
            }
        }
}

// --------- softmax over last dim (512): 1 warp/row, 8 rows/block, no smem -------
__global__ __launch_bounds__(256) void softmax_kernel(
    float* __restrict__ P, __half* __restrict__ Ph) {
    const size_t row = (size_t)blockIdx.x * 8 + (threadIdx.x >> 5);
    const int lane = threadIdx.x & 31;
    float* p = P + row * 512;
    __half* ph = Ph + row * 512;

    float4 xv[4];
#pragma unroll
    for (int it = 0; it < 4; it++) xv[it] = ((float4*)p)[lane + it * 32];

    float m = -1e30f;
#pragma unroll
    for (int it = 0; it < 4; it++)
        m = fmaxf(m, fmaxf(fmaxf(xv[it].x, xv[it].y), fmaxf(xv[it].z, xv[it].w)));
#pragma unroll
    for (int o = 16; o > 0; o >>= 1) m = fmaxf(m, __shfl_xor_sync(0xffffffffu, m, o));

    float s = 0.f;
#pragma unroll
    for (int it = 0; it < 4; it++) {
        xv[it].x = expf(xv[it].x - m); xv[it].y = expf(xv[it].y - m);
        xv[it].z = expf(xv[it].z - m); xv[it].w = expf(xv[it].w - m);
        s += xv[it].x + xv[it].y + xv[it].z + xv[it].w;
    }
#pragma unroll
    for (int o = 16; o > 0; o >>= 1) s += __shfl_xor_sync(0xffffffffu, s, o);
    float inv = 1.0f / s;

#pragma unroll
    for (int it = 0; it < 4; it++) {
        xv[it].x *= inv; xv[it].y *= inv; xv[it].z *= inv; xv[it].w *= inv;
        ((float4*)p)[lane + it * 32] = xv[it];
        __half2 h0 = __float22half2_rn(make_float2(xv[it].x, xv[it].y));
        __half2 h1 = __float22half2_rn(make_float2(xv[it].z, xv[it].w));
        uint2 u; u.x = *(uint32_t*)&h0; u.y = *(uint32_t*)&h1;
        *(uint2*)(ph + (lane + it * 32) * 4) = u;
    }
}

// ===== context: ctx[r,i,n,h,d] = sum_j P[h,n,i,j] v[r,j,n,h,d]  (trans-B) ========
__global__ __launch_bounds__(256, 2) void context_gemm(
    const __half* __restrict__ Ph, const __half* __restrict__ v,
    __half* __restrict__ ctx)
{
    extern __shared__ __align__(16) char smem[];
    const int tid = threadIdx.x, warp = tid >> 5, lane = tid & 31;
    const int wm = (warp >> 2) * 64, wn = (warp & 3) * 32;
    const int i0 = blockIdx.x * 128;
    const int c0 = blockIdx.y * 128;      // over r*32+d (2048 wide)
    const int r0 = c0 >> 5;               // 4 r values per tile
    const int z = blockIdx.z, h = z >> 2, n = z & 3;
    const int nh = h * 4 + n;

    float acc[4][4][4];
#pragma unroll
    for (int fq = 0; fq < 4; fq++)
#pragma unroll
        for (int g = 0; g < 4; g++)
#pragma unroll
            for (int c = 0; c < 4; c++) acc[fq][g][c] = 0.f;

    gemm_main<32, 5, true>(
        Ph + ((size_t)nh * 512 + i0) * 512, 512, 32 * 512, 0, 32,
        v + ((size_t)r0 * 512 * 4 + n) * 256 + h * 32, 1024, 524288, 0, 32768,
        16, smem_u32(smem), tid, wm, wn, lane, acc);

    const int grp = lane >> 2, qid = lane & 3;
#pragma unroll
    for (int fq = 0; fq < 4; fq++)
#pragma unroll
        for (int rr = 0; rr < 2; rr++) {
            int i = i0 + wm + fq * 16 + grp + rr * 8;
#pragma unroll
            for (int g = 0; g < 4; g++) {
                int col = c0 + wn + g * 8 + qid * 2;
                int r = col >> 5, d = col & 31;
                float2 o;
                o.x = acc[fq][g][rr * 2 + 0];
                o.y = acc[fq][g][rr * 2 + 1];
                *(__half2*)(ctx + (((size_t)r * 512 + i) * 4 + n) * 256 + h * 32 + d) =
                    __float22half2_rn(o);
            }
        }
}

// --------------------------------- launch ---------------------------------------
extern "C" void kernel_launch(void* const* d_in, const int* in_sizes, int n_in,
                              void* d_out, int out_size) {
    const float* x   = (const float*)d_in[0];
    const int*   dst = (const int*)  d_in[1];
    const float* Wq  = (const float*)d_in[2];
    const float* bq  = (const float*)d_in[3];
    const float* Wk  = (const float*)d_in[4];
    const float* bk  = (const float*)d_in[5];
    const float* Wv  = (const float*)d_in[6];
    const float* bv  = (const float*)d_in[7];
    const float* Wo  = (const float*)d_in[8];
    const float* bo  = (const float*)d_in[9];
    const float* rel = (const float*)d_in[10];
    float* out = (float*)d_out;

    __half *xh, *wh, *q, *k, *v, *ctx, *ph;
    float* probs_fallback;
    unsigned char* bkt;
    cudaGetSymbolAddress((void**)&xh,  gh_x);
    cudaGetSymbolAddress((void**)&wh,  gh_w);
    cudaGetSymbolAddress((void**)&q,   gh_q);
    cudaGetSymbolAddress((void**)&k,   gh_k);
    cudaGetSymbolAddress((void**)&v,   gh_v);
    cudaGetSymbolAddress((void**)&ctx, gh_ctx);
    cudaGetSymbolAddress((void**)&ph,  gh_pr);
    cudaGetSymbolAddress((void**)&probs_fallback, g_probs);
    cudaGetSymbolAddress((void**)&bkt, g_bkt);

    float* probs = ((size_t)out_size >= OUT_ELEMS + PROB_ELEMS) ? (out + OUT_ELEMS)
                                                                : probs_fallback;

    cudaFuncSetAttribute(proj_qkv,     cudaFuncAttributeMaxDynamicSharedMemorySize, SM64);
    cudaFuncSetAttribute(proj_out,     cudaFuncAttributeMaxDynamicSharedMemorySize, SM64);
    cudaFuncSetAttribute(logits_gemm,  cudaFuncAttributeMaxDynamicSharedMemorySize, SM64);
    cudaFuncSetAttribute(context_gemm, cudaFuncAttributeMaxDynamicSharedMemorySize, SM32);

    const float scaleq = 0.022097086912079608f;  // D^-0.5 / sqrt(R)
    dim3 blk(256);

    prep_kernel<<<XBLK + WBLK + BBLK, blk>>>(x, xh, Wq, Wk, Wv, Wo, wh, dst, bkt);

    proj_qkv<<<dim3(T_TOK / 128, E_DIM / 128, 3), blk, SM64>>>(
        xh, wh, bq, bk, bv, q, k, v, scaleq);

    logits_gemm<<<dim3(I_DIM / 128, I_DIM / 128, N_DIM * H_DIM), blk, SM64>>>(
        q, k, bkt, rel, probs);
    softmax_kernel<<<(H_DIM * N_DIM * I_DIM) / 8, blk>>>(probs, ph);
    context_gemm<<<dim3(I_DIM / 128, (R_DIM * D_DIM) / 128, N_DIM * H_DIM), blk, SM32>>>(
        ph, v, ctx);

    proj_out<<<dim3(T_TOK / 128, E_DIM / 128), blk, SM64>>>(
        ctx, wh + 3 * E_DIM * E_DIM, bo, out);
}